// round 7
// baseline (speedup 1.0000x reference)
#include <cuda_runtime.h>
#include <math.h>
#include <stdint.h>

// ---------------------------------------------------------------------------
// GCNEncoder on tensor cores (tf32 mma.sync), cp.async 3-stage pipeline,
// ldmatrix fragment loads. Both GEMM operands staged K-major [row][k].
// Block tile 128(M) x 256(N) x 32(K); 8 warps (2m x 4n); warp tile 64x64.
// Shapes: B=32, N=1024, D=1024, D_FF=512, L=2.
// ---------------------------------------------------------------------------

#define BM 128
#define BN 256
#define BK 32
#define RK_STRIDE 36                  // [row][k] padded (floats)
#define STAGE_A_WORDS (128 * 36)      // 4608
#define STAGE_B_WORDS (256 * 36)      // 9216
#define STAGE_WORDS   (STAGE_A_WORDS + STAGE_B_WORDS)
#define NSTAGE 3
#define SMEM_BYTES    (NSTAGE * STAGE_WORDS * 4)   // 165,888 B

static const int BB   = 32;
static const int NN_  = 1024;
static const int DD   = 1024;
static const int DFF  = 512;
static const long long MTOT = 32768; // B*N

// Scratch (device globals; no allocations allowed)
__device__ float g_X [32768ll * 1024];
__device__ float g_XT[32768ll * 1024];
__device__ float g_Q [32768ll * 512];
__device__ float g_K [32768ll * 512];
__device__ float g_S [32ll * 1024 * 1024];
__device__ float g_C [32768ll * 1024];
__device__ float g_C2[32768ll * 1024];
__device__ float g_NF[32768ll * 1024];    // tf32-rounded node_fts
__device__ float g_W [5ll * 1024 * 1024]; // tf32-rounded transposed weights

__device__ __forceinline__ uint32_t f2tf32(float x) {
    uint32_t t;
    asm("cvt.rna.tf32.f32 %0, %1;" : "=r"(t) : "f"(x));
    return t;
}
__device__ __forceinline__ float tf32r(float x) { return __uint_as_float(f2tf32(x)); }

__device__ __forceinline__ void cp_async16(float* smem_ptr, const float* gmem) {
    uint32_t s = (uint32_t)__cvta_generic_to_shared(smem_ptr);
    asm volatile("cp.async.cg.shared.global [%0], [%1], 16;\n" :: "r"(s), "l"(gmem));
}
__device__ __forceinline__ void cp_commit() {
    asm volatile("cp.async.commit_group;\n" ::: "memory");
}
template <int N>
__device__ __forceinline__ void cp_wait() {
    asm volatile("cp.async.wait_group %0;\n" :: "n"(N) : "memory");
}

__device__ __forceinline__ void ldsm_x4(uint32_t& r0, uint32_t& r1,
                                        uint32_t& r2, uint32_t& r3, uint32_t addr) {
    asm volatile("ldmatrix.sync.aligned.m8n8.x4.shared.b16 {%0,%1,%2,%3}, [%4];"
                 : "=r"(r0), "=r"(r1), "=r"(r2), "=r"(r3) : "r"(addr));
}

__device__ __forceinline__ void mma_tf32(float c[4], const uint32_t a[4],
                                         const uint32_t b[2]) {
    asm volatile(
        "mma.sync.aligned.m16n8k8.row.col.f32.tf32.tf32.f32 "
        "{%0,%1,%2,%3}, {%4,%5,%6,%7}, {%8,%9}, {%0,%1,%2,%3};\n"
        : "+f"(c[0]), "+f"(c[1]), "+f"(c[2]), "+f"(c[3])
        : "r"(a[0]), "r"(a[1]), "r"(a[2]), "r"(a[3]),
          "r"(b[0]), "r"(b[1]));
}

// ---------------------------------------------------------------------------
// Elementwise tf32 rounding
// ---------------------------------------------------------------------------
__global__ void __launch_bounds__(256)
tf32_round_kernel(const float* __restrict__ in, float* __restrict__ out,
                  long long n)
{
    long long i = ((long long)blockIdx.x * blockDim.x + threadIdx.x) * 4;
    if (i >= n) return;
    float4 v = *(const float4*)&in[i];
    v.x = tf32r(v.x); v.y = tf32r(v.y); v.z = tf32r(v.z); v.w = tf32r(v.w);
    *(float4*)&out[i] = v;
}

// ---------------------------------------------------------------------------
// Batched transpose with tf32 rounding: in[z][R][Cc] -> out[z][Cc][R]
// block 256 = 32x8, tile 32x32. R%32==0, Cc%32==0.
// ---------------------------------------------------------------------------
__global__ void __launch_bounds__(256)
transpose_tf32_kernel(const float* __restrict__ in, float* __restrict__ out,
                      int R, int Cc)
{
    __shared__ float t[32][33];
    long long zo = (long long)blockIdx.z * R * Cc;
    int r0 = blockIdx.y * 32, c0 = blockIdx.x * 32;
    int tx = threadIdx.x & 31, ty = threadIdx.x >> 5;
#pragma unroll
    for (int i = 0; i < 4; i++)
        t[ty + i * 8][tx] = in[zo + (long long)(r0 + ty + i * 8) * Cc + c0 + tx];
    __syncthreads();
#pragma unroll
    for (int i = 0; i < 4; i++)
        out[zo + (long long)(c0 + ty + i * 8) * R + r0 + tx] = tf32r(t[tx][ty + i * 8]);
}

// ---------------------------------------------------------------------------
// Tensor-core GEMM. C = alpha * A(MxK) @ Bt(NxK)^T (+bias)(+relu)(+tf32 round)
// Both operands row-major K-major, values already tf32-rounded.
// M%128==0, N%256==0, K%32==0. Batch via blockIdx.z strides. 256 threads.
// ---------------------------------------------------------------------------
template <bool RELU, bool BIAS, bool CVT_OUT>
__global__ void __launch_bounds__(256, 1)
gemm_tc(const float* __restrict__ A, const float* __restrict__ Bt,
        const float* __restrict__ bias, float* __restrict__ C,
        int M, int N, int K,
        long long sA, long long sB, long long sC, float alpha)
{
    extern __shared__ float smem[];

    const int bz = blockIdx.z;
    A  += (long long)bz * sA;
    Bt += (long long)bz * sB;
    C  += (long long)bz * sC;

    const int tid  = threadIdx.x;
    const int lane = tid & 31;
    const int wid  = tid >> 5;
    const int warpM = wid >> 2;  // 0..1
    const int warpN = wid & 3;   // 0..3
    const int rowBase = blockIdx.y * BM;
    const int colBase = blockIdx.x * BN;

    float acc[4][8][4];
#pragma unroll
    for (int i = 0; i < 4; i++)
#pragma unroll
        for (int j = 0; j < 8; j++)
#pragma unroll
            for (int r = 0; r < 4; r++) acc[i][j][r] = 0.f;

    const int lq = lane >> 2;   // 0..7
    const int lr = lane & 3;    // 0..3

    // ldmatrix lane-relative offset (floats): row (l&7) + 8*bit3, k + 4*bit4
    const int lofs = ((lane & 7) + ((lane >> 3) & 1) * 8) * RK_STRIDE
                   + ((lane >> 4) & 1) * 4;

    const uint32_t smem_base_u32 = (uint32_t)__cvta_generic_to_shared(smem);
    const int kTiles = K / BK;

    auto issue_stage = [&](int it) {
        float* As = smem + (it % NSTAGE) * STAGE_WORDS;
        float* Bs = As + STAGE_A_WORDS;
        const int k0 = it * BK;
        // A tile: 128 rows x 32 k
#pragma unroll
        for (int i = 0; i < 4; i++) {
            int gid = tid + i * 256;
            int r = gid >> 3;              // 0..127
            int c = (gid & 7) * 4;         // 0..28
            cp_async16(&As[r * RK_STRIDE + c],
                       &A[(long long)(rowBase + r) * K + k0 + c]);
        }
        // B tile: 256 n-rows x 32 k
#pragma unroll
        for (int i = 0; i < 8; i++) {
            int gid = tid + i * 256;
            int n = gid >> 3;              // 0..255
            int c = (gid & 7) * 4;         // 0..28
            cp_async16(&Bs[n * RK_STRIDE + c],
                       &Bt[(long long)(colBase + n) * K + k0 + c]);
        }
        cp_commit();
    };

    issue_stage(0);
    issue_stage(1);

    for (int it = 0; it < kTiles; it++) {
        if (it + 1 < kTiles) cp_wait<1>(); else cp_wait<0>();
        __syncthreads();
        if (it + 2 < kTiles) issue_stage(it + 2);

        const uint32_t sA_u32 = smem_base_u32
            + (uint32_t)((it % NSTAGE) * STAGE_WORDS) * 4u;
        const uint32_t sB_u32 = sA_u32 + STAGE_A_WORDS * 4u;

#pragma unroll
        for (int ks = 0; ks < 4; ks++) {
            const int kb = ks * 8;
            uint32_t afr[4][4];
#pragma unroll
            for (int i = 0; i < 4; i++) {
                uint32_t addr = sA_u32 +
                    (uint32_t)(((warpM * 64 + i * 16) * RK_STRIDE + kb + lofs) * 4);
                ldsm_x4(afr[i][0], afr[i][1], afr[i][2], afr[i][3], addr);
            }
            uint32_t bfr[8][2];
#pragma unroll
            for (int p = 0; p < 4; p++) {   // each x4 covers j=2p, 2p+1
                uint32_t addr = sB_u32 +
                    (uint32_t)(((warpN * 64 + p * 16) * RK_STRIDE + kb + lofs) * 4);
                uint32_t r0, r1, r2, r3;
                ldsm_x4(r0, r1, r2, r3, addr);
                bfr[2 * p][0] = r0; bfr[2 * p + 1][0] = r1;
                bfr[2 * p][1] = r2; bfr[2 * p + 1][1] = r3;
            }
#pragma unroll
            for (int i = 0; i < 4; i++)
#pragma unroll
                for (int j = 0; j < 8; j++)
                    mma_tf32(acc[i][j], afr[i], bfr[j]);
        }
    }

    // ---- epilogue
#pragma unroll
    for (int i = 0; i < 4; i++) {
        int row0 = rowBase + warpM * 64 + i * 16 + lq;
#pragma unroll
        for (int j = 0; j < 8; j++) {
            int col = colBase + warpN * 64 + j * 8 + lr * 2;
            float b0 = 0.f, b1 = 0.f;
            if (BIAS) { b0 = bias[col]; b1 = bias[col + 1]; }
            float2 v;
            v.x = acc[i][j][0] * alpha + b0;
            v.y = acc[i][j][1] * alpha + b1;
            if (RELU) { v.x = fmaxf(v.x, 0.f); v.y = fmaxf(v.y, 0.f); }
            if (CVT_OUT) { v.x = tf32r(v.x); v.y = tf32r(v.y); }
            *(float2*)&C[(long long)row0 * N + col] = v;
            v.x = acc[i][j][2] * alpha + b0;
            v.y = acc[i][j][3] * alpha + b1;
            if (RELU) { v.x = fmaxf(v.x, 0.f); v.y = fmaxf(v.y, 0.f); }
            if (CVT_OUT) { v.x = tf32r(v.x); v.y = tf32r(v.y); }
            *(float2*)&C[(long long)(row0 + 8) * N + col] = v;
        }
    }
}

// ---------------------------------------------------------------------------
// Block-wide reduction helpers (blockDim.x == 256)
// ---------------------------------------------------------------------------
__device__ __forceinline__ float block_reduce_max(float v, float* red) {
    int lane = threadIdx.x & 31, wid = threadIdx.x >> 5;
#pragma unroll
    for (int o = 16; o > 0; o >>= 1) v = fmaxf(v, __shfl_xor_sync(0xffffffffu, v, o));
    if (lane == 0) red[wid] = v;
    __syncthreads();
    if (wid == 0) {
        float x = (lane < 8) ? red[lane] : -INFINITY;
#pragma unroll
        for (int o = 4; o > 0; o >>= 1) x = fmaxf(x, __shfl_xor_sync(0xffffffffu, x, o));
        if (lane == 0) red[0] = x;
    }
    __syncthreads();
    float r = red[0];
    __syncthreads();
    return r;
}
__device__ __forceinline__ float block_reduce_sum(float v, float* red) {
    int lane = threadIdx.x & 31, wid = threadIdx.x >> 5;
#pragma unroll
    for (int o = 16; o > 0; o >>= 1) v += __shfl_xor_sync(0xffffffffu, v, o);
    if (lane == 0) red[wid] = v;
    __syncthreads();
    if (wid == 0) {
        float x = (lane < 8) ? red[lane] : 0.f;
#pragma unroll
        for (int o = 4; o > 0; o >>= 1) x += __shfl_xor_sync(0xffffffffu, x, o);
        if (lane == 0) red[0] = x;
    }
    __syncthreads();
    float r = red[0];
    __syncthreads();
    return r;
}

// ---------------------------------------------------------------------------
// Masked softmax over each 1024-wide row of S (in place). mask = (rel == 0)
// ---------------------------------------------------------------------------
__global__ void __launch_bounds__(256)
softmax_mask_kernel(float* __restrict__ S, const float* __restrict__ rel)
{
    __shared__ float red[8];
    long long row = blockIdx.x;
    float* s = S + row * 1024;
    const float* r = rel + row * 1024;
    int tid = threadIdx.x;

    float4 sv = *(const float4*)&s[tid * 4];
    float4 mv = *(const float4*)&r[tid * 4];
    float v0 = (mv.x != 0.f) ? sv.x : -INFINITY;
    float v1 = (mv.y != 0.f) ? sv.y : -INFINITY;
    float v2 = (mv.z != 0.f) ? sv.z : -INFINITY;
    float v3 = (mv.w != 0.f) ? sv.w : -INFINITY;

    float vmax = block_reduce_max(fmaxf(fmaxf(v0, v1), fmaxf(v2, v3)), red);

    float e0 = (mv.x != 0.f) ? expf(v0 - vmax) : 0.f;
    float e1 = (mv.y != 0.f) ? expf(v1 - vmax) : 0.f;
    float e2 = (mv.z != 0.f) ? expf(v2 - vmax) : 0.f;
    float e3 = (mv.w != 0.f) ? expf(v3 - vmax) : 0.f;

    float sum = block_reduce_sum(e0 + e1 + e2 + e3, red);
    float inv = (sum > 0.f) ? (1.f / sum) : 0.f;

    float4 o;
    o.x = tf32r(e0 * inv); o.y = tf32r(e1 * inv);
    o.z = tf32r(e2 * inv); o.w = tf32r(e3 * inv);
    *(float4*)&s[tid * 4] = o;
}

// ---------------------------------------------------------------------------
// out[row] = LayerNorm(X[row] + Cx[row]) * g + b   (row length 1024)
// ---------------------------------------------------------------------------
template <bool CVT>
__global__ void __launch_bounds__(256)
add_ln_kernel(const float* __restrict__ X, const float* __restrict__ Cx,
              const float* __restrict__ g, const float* __restrict__ b,
              float* __restrict__ out)
{
    __shared__ float red[8];
    long long row = blockIdx.x;
    int tid = threadIdx.x;

    float4 xv = *(const float4*)&X [row * 1024 + tid * 4];
    float4 cv = *(const float4*)&Cx[row * 1024 + tid * 4];
    float v0 = xv.x + cv.x, v1 = xv.y + cv.y, v2 = xv.z + cv.z, v3 = xv.w + cv.w;

    float sum  = block_reduce_sum(v0 + v1 + v2 + v3, red);
    float ssq  = block_reduce_sum(v0 * v0 + v1 * v1 + v2 * v2 + v3 * v3, red);
    float mean = sum * (1.f / 1024.f);
    float var  = ssq * (1.f / 1024.f) - mean * mean;
    float rstd = rsqrtf(var + 1e-5f);

    float4 gv = *(const float4*)&g[tid * 4];
    float4 bv = *(const float4*)&b[tid * 4];
    float4 o;
    o.x = (v0 - mean) * rstd * gv.x + bv.x;
    o.y = (v1 - mean) * rstd * gv.y + bv.y;
    o.z = (v2 - mean) * rstd * gv.z + bv.z;
    o.w = (v3 - mean) * rstd * gv.w + bv.w;
    if (CVT) { o.x = tf32r(o.x); o.y = tf32r(o.y); o.z = tf32r(o.z); o.w = tf32r(o.w); }
    *(float4*)&out[row * 1024 + tid * 4] = o;
}

// ---------------------------------------------------------------------------
extern "C" void kernel_launch(void* const* d_in, const int* in_sizes, int n_in,
                              void* d_out, int out_size)
{
    const float* node_fts = (const float*)d_in[0];
    const float* rel      = (const float*)d_in[1];
    const float* W_emb    = (const float*)d_in[2];
    const float* b_emb    = (const float*)d_in[3];
    const float* Wq       = (const float*)d_in[4];
    const float* bq       = (const float*)d_in[5];
    const float* Wk       = (const float*)d_in[6];
    const float* bk       = (const float*)d_in[7];
    const float* Wc       = (const float*)d_in[8];
    const float* ln_g     = (const float*)d_in[9];
    const float* ln_b     = (const float*)d_in[10];
    float* out = (float*)d_out;

    float *X, *XT, *Q, *K, *S, *C, *C2, *NF, *W;
    cudaGetSymbolAddress((void**)&X,  g_X);
    cudaGetSymbolAddress((void**)&XT, g_XT);
    cudaGetSymbolAddress((void**)&Q,  g_Q);
    cudaGetSymbolAddress((void**)&K,  g_K);
    cudaGetSymbolAddress((void**)&S,  g_S);
    cudaGetSymbolAddress((void**)&C,  g_C);
    cudaGetSymbolAddress((void**)&C2, g_C2);
    cudaGetSymbolAddress((void**)&NF, g_NF);
    cudaGetSymbolAddress((void**)&W,  g_W);

    static bool attr_done = false;
    if (!attr_done) {
        cudaFuncSetAttribute(gemm_tc<true,  true,  true >,
                             cudaFuncAttributeMaxDynamicSharedMemorySize, SMEM_BYTES);
        cudaFuncSetAttribute(gemm_tc<false, true,  true >,
                             cudaFuncAttributeMaxDynamicSharedMemorySize, SMEM_BYTES);
        cudaFuncSetAttribute(gemm_tc<false, false, false>,
                             cudaFuncAttributeMaxDynamicSharedMemorySize, SMEM_BYTES);
        cudaFuncSetAttribute(gemm_tc<false, false, true >,
                             cudaFuncAttributeMaxDynamicSharedMemorySize, SMEM_BYTES);
        attr_done = true;
    }

    dim3 blk(256);
    const float inv_sqrt_dff = 1.0f / sqrtf((float)DFF);

    // Transposed tf32 weights (packed in g_W); all stored [N, K] K-major.
    float* WembT = W;                        // [1024,1024]
    float* WqT   = W + 1024ll * 1024;        // [2][512,1024]
    float* WkT   = W + 2048ll * 1024;        // [2][512,1024]
    float* WcT   = W + 3072ll * 1024;        // [2][1024,1024]

    // Pre-round A-side input; pre-round+transpose all weights
    tf32_round_kernel<<<(int)(MTOT * DD / 1024), blk>>>(node_fts, NF, MTOT * DD);
    transpose_tf32_kernel<<<dim3(32, 32, 1), blk>>>(W_emb, WembT, 1024, 1024);
    transpose_tf32_kernel<<<dim3(16, 32, 2), blk>>>(Wq, WqT, 1024, 512);
    transpose_tf32_kernel<<<dim3(16, 32, 2), blk>>>(Wk, WkT, 1024, 512);
    transpose_tf32_kernel<<<dim3(32, 32, 2), blk>>>(Wc, WcT, 1024, 1024);

    // Embedding: X = tf32(relu(NF @ W_emb + b_emb))   [32768 x 1024 x 1024]
    gemm_tc<true, true, true>
        <<<dim3(DD / BN, (int)(MTOT / BM), 1), blk, SMEM_BYTES>>>(
            NF, WembT, b_emb, X, (int)MTOT, DD, DD, 0, 0, 0, 1.0f);

    for (int l = 0; l < 2; l++) {
        const float* WqTl = WqT + (long long)l * DD * DFF;
        const float* bql  = bq + (long long)l * DFF;
        const float* WkTl = WkT + (long long)l * DD * DFF;
        const float* bkl  = bk + (long long)l * DFF;
        const float* WcTl = WcT + (long long)l * DD * DD;
        const float* gl   = ln_g + (long long)l * DD;
        const float* bl   = ln_b + (long long)l * DD;

        // XT[b][d][n] = X[b][n][d]  (B operand for C = S @ X)
        transpose_tf32_kernel<<<dim3(32, 32, 32), blk>>>(X, XT, 1024, 1024);

        // Q = tf32(X @ Wq + bq); K likewise     [32768 x 512 x 1024]
        gemm_tc<false, true, true>
            <<<dim3(DFF / BN, (int)(MTOT / BM), 1), blk, SMEM_BYTES>>>(
                X, WqTl, bql, Q, (int)MTOT, DFF, DD, 0, 0, 0, 1.0f);
        gemm_tc<false, true, true>
            <<<dim3(DFF / BN, (int)(MTOT / BM), 1), blk, SMEM_BYTES>>>(
                X, WkTl, bkl, K, (int)MTOT, DFF, DD, 0, 0, 0, 1.0f);

        // S = (Q @ K^T) / sqrt(DFF)             [32 x (1024 x 1024 x 512)]
        gemm_tc<false, false, false>
            <<<dim3(NN_ / BN, NN_ / BM, BB), blk, SMEM_BYTES>>>(
                Q, K, nullptr, S, NN_, NN_, DFF,
                (long long)NN_ * DFF, (long long)NN_ * DFF,
                (long long)NN_ * NN_, inv_sqrt_dff);

        // masked softmax over rows of S (tf32-rounded output)
        softmax_mask_kernel<<<(int)MTOT, blk>>>(S, rel);

        // C = tf32(S @ X)                        [32 x (1024 x 1024 x 1024)]
        gemm_tc<false, false, true>
            <<<dim3(DD / BN, NN_ / BM, BB), blk, SMEM_BYTES>>>(
                S, XT, nullptr, C, NN_, DD, NN_,
                (long long)NN_ * NN_, (long long)DD * NN_,
                (long long)NN_ * DD, 1.0f);

        // C2 = C @ Wc                            [32768 x 1024 x 1024]
        gemm_tc<false, false, false>
            <<<dim3(DD / BN, (int)(MTOT / BM), 1), blk, SMEM_BYTES>>>(
                C, WcTl, nullptr, C2, (int)MTOT, DD, DD, 0, 0, 0, 1.0f);

        // X = LN(X + C2) * g + b  (layer 0: tf32-rounded; layer 1 -> d_out fp32)
        if (l == 0) add_ln_kernel<true ><<<(int)MTOT, blk>>>(X, C2, gl, bl, X);
        else        add_ln_kernel<false><<<(int)MTOT, blk>>>(X, C2, gl, bl, out);
    }
}

// round 8
// speedup vs baseline: 1.8509x; 1.8509x over previous
#include <cuda_runtime.h>
#include <cuda_fp16.h>
#include <math.h>
#include <stdint.h>

// ---------------------------------------------------------------------------
// GCNEncoder on fp16 tensor cores (mma.m16n8k16, fp32 accum), cp.async
// 3-stage pipeline, ldmatrix fragment loads (trans variant for K-major B).
// Block tile 128(M) x 256(N) x 64(K); 8 warps (2m x 4n); warp tile 64x64.
// Shapes: B=32, N=1024, D=1024, D_FF=512, L=2.
// ---------------------------------------------------------------------------

#define BM 128
#define BN 256
#define BKH 64                         // k halves per stage (128B rows)
#define A_STRIDE_H  72                 // [row][k] halves, 144B padded
#define BKN_STRIDE_H 264               // [k][n] halves, 528B padded
#define A_BYTES     (128 * 144)        // 18432
#define BNK_BYTES   (256 * 144)        // 36864
#define STAGE_BYTES (A_BYTES + BNK_BYTES)  // 55296 (>= A + B_KN = 52224)
#define NSTAGE 3
#define SMEM_BYTES  (NSTAGE * STAGE_BYTES) // 165888

static const int BB   = 32;
static const int NN_  = 1024;
static const int DD   = 1024;
static const int DFF  = 512;
static const long long MTOT = 32768;

// Scratch (device globals; no allocations allowed)
__device__ __half g_Xh [32768ll * 1024];
__device__ __half g_Qh [32768ll * 512];
__device__ __half g_Kh [32768ll * 512];
__device__ float  g_S  [32ll * 1024 * 1024];   // raw scores (f32)
__device__ __half g_Sh [32ll * 1024 * 1024];   // softmaxed (fp16)
__device__ __half g_Ch [32768ll * 1024];
__device__ float  g_C2 [32768ll * 1024];
__device__ __half g_NFh[32768ll * 1024];
__device__ __half g_Wh [5ll * 1024 * 1024];    // transposed fp16 weights

// ---------------------------------------------------------------------------
__device__ __forceinline__ void cp_async16(uint32_t saddr, const void* g) {
    asm volatile("cp.async.cg.shared.global [%0], [%1], 16;\n" :: "r"(saddr), "l"(g));
}
__device__ __forceinline__ void cp_commit() {
    asm volatile("cp.async.commit_group;\n" ::: "memory");
}
template <int N>
__device__ __forceinline__ void cp_wait() {
    asm volatile("cp.async.wait_group %0;\n" :: "n"(N) : "memory");
}
__device__ __forceinline__ void ldsm_x4(uint32_t& r0, uint32_t& r1,
                                        uint32_t& r2, uint32_t& r3, uint32_t a) {
    asm volatile("ldmatrix.sync.aligned.m8n8.x4.shared.b16 {%0,%1,%2,%3}, [%4];"
                 : "=r"(r0), "=r"(r1), "=r"(r2), "=r"(r3) : "r"(a));
}
__device__ __forceinline__ void ldsm_x4_t(uint32_t& r0, uint32_t& r1,
                                          uint32_t& r2, uint32_t& r3, uint32_t a) {
    asm volatile("ldmatrix.sync.aligned.m8n8.x4.trans.shared.b16 {%0,%1,%2,%3}, [%4];"
                 : "=r"(r0), "=r"(r1), "=r"(r2), "=r"(r3) : "r"(a));
}
__device__ __forceinline__ void mma_f16(float c[4], const uint32_t a[4],
                                        const uint32_t b[2]) {
    asm volatile(
        "mma.sync.aligned.m16n8k16.row.col.f32.f16.f16.f32 "
        "{%0,%1,%2,%3}, {%4,%5,%6,%7}, {%8,%9}, {%0,%1,%2,%3};\n"
        : "+f"(c[0]), "+f"(c[1]), "+f"(c[2]), "+f"(c[3])
        : "r"(a[0]), "r"(a[1]), "r"(a[2]), "r"(a[3]),
          "r"(b[0]), "r"(b[1]));
}

// ---------------------------------------------------------------------------
// fp16 GEMM. C = alpha * A(MxK) @ B (+bias)(+relu); OUT_HALF picks C dtype.
// B_KN=false: B is [N][K] halves (K-major)  -> plain ldmatrix.
// B_KN=true : B is [K][N] halves            -> ldmatrix.trans.
// M%128==0, N%256==0, K%64==0. Batch via blockIdx.z strides. 256 threads.
// ---------------------------------------------------------------------------
template <bool B_KN, bool RELU, bool BIAS, bool OUT_HALF>
__global__ void __launch_bounds__(256, 1)
gemm_h(const __half* __restrict__ A, const __half* __restrict__ B,
       const float* __restrict__ bias, void* __restrict__ Cout,
       int M, int N, int K,
       long long sA, long long sB, long long sC, float alpha)
{
    extern __shared__ char smem[];
    const uint32_t sbase = (uint32_t)__cvta_generic_to_shared(smem);

    const int bz = blockIdx.z;
    A += (long long)bz * sA;
    B += (long long)bz * sB;

    const int tid  = threadIdx.x;
    const int lane = tid & 31;
    const int wid  = tid >> 5;
    const int warpM = wid >> 2;
    const int warpN = wid & 3;
    const int rowBase = blockIdx.y * BM;
    const int colBase = blockIdx.x * BN;

    float acc[4][8][4];
#pragma unroll
    for (int i = 0; i < 4; i++)
#pragma unroll
        for (int j = 0; j < 8; j++)
#pragma unroll
            for (int r = 0; r < 4; r++) acc[i][j][r] = 0.f;

    const int lq = lane >> 2;
    const int lr = lane & 3;

    // ldmatrix lane offsets (bytes)
    const int ofsA = ((lane & 7) + ((lane >> 3) & 1) * 8) * 144
                   + ((lane >> 4) & 1) * 16;              // rows=m/n, stride 144B
    const int ofsT = ((lane & 7) + ((lane >> 4) & 1) * 8) * 528
                   + ((lane >> 3) & 1) * 16;              // rows=k, stride 528B

    const int kTiles = K / BKH;

    auto issue_stage = [&](int it) {
        const uint32_t sb = sbase + (it % NSTAGE) * STAGE_BYTES;
        const int k0 = it * BKH;
        // A tile: 128 rows x 64 halves (8 x 16B chunks per row)
#pragma unroll
        for (int i = 0; i < 4; i++) {
            int gid = tid + i * 256;
            int r = gid >> 3, c = gid & 7;
            cp_async16(sb + r * 144 + c * 16,
                       &A[(long long)(rowBase + r) * K + k0 + c * 8]);
        }
        if (!B_KN) {
            // B [N][K]: 256 rows x 64 halves
#pragma unroll
            for (int i = 0; i < 8; i++) {
                int gid = tid + i * 256;
                int r = gid >> 3, c = gid & 7;
                cp_async16(sb + A_BYTES + r * 144 + c * 16,
                           &B[(long long)(colBase + r) * K + k0 + c * 8]);
            }
        } else {
            // B [K][N]: 64 k-rows x 256 halves (32 chunks per row)
#pragma unroll
            for (int i = 0; i < 8; i++) {
                int gid = tid + i * 256;
                int r = gid >> 5, c = gid & 31;
                cp_async16(sb + A_BYTES + r * 528 + c * 16,
                           &B[(long long)(k0 + r) * N + colBase + c * 8]);
            }
        }
        cp_commit();
    };

    issue_stage(0);
    issue_stage(1);

    for (int it = 0; it < kTiles; it++) {
        if (it + 1 < kTiles) cp_wait<1>(); else cp_wait<0>();
        __syncthreads();
        if (it + 2 < kTiles) issue_stage(it + 2);

        const uint32_t sA = sbase + (it % NSTAGE) * STAGE_BYTES;
        const uint32_t sB = sA + A_BYTES;

#pragma unroll
        for (int ks = 0; ks < 4; ks++) {          // 4 x k16 per 64-k tile
            uint32_t afr[4][4];
#pragma unroll
            for (int i = 0; i < 4; i++) {
                uint32_t addr = sA + (uint32_t)((warpM * 64 + i * 16) * 144
                                                + ks * 32 + ofsA);
                ldsm_x4(afr[i][0], afr[i][1], afr[i][2], afr[i][3], addr);
            }
            uint32_t bfr[8][2];
            if (!B_KN) {
#pragma unroll
                for (int p = 0; p < 4; p++) {
                    uint32_t addr = sB + (uint32_t)((warpN * 64 + p * 16) * 144
                                                    + ks * 32 + ofsA);
                    uint32_t r0, r1, r2, r3;
                    ldsm_x4(r0, r1, r2, r3, addr);
                    bfr[2 * p][0] = r0; bfr[2 * p + 1][0] = r1;
                    bfr[2 * p][1] = r2; bfr[2 * p + 1][1] = r3;
                }
            } else {
#pragma unroll
                for (int p = 0; p < 4; p++) {
                    uint32_t addr = sB + (uint32_t)(ks * 16 * 528
                                                    + (warpN * 64 + p * 16) * 2 + ofsT);
                    uint32_t r0, r1, r2, r3;
                    ldsm_x4_t(r0, r1, r2, r3, addr);
                    bfr[2 * p][0] = r0; bfr[2 * p + 1][0] = r1;
                    bfr[2 * p][1] = r2; bfr[2 * p + 1][1] = r3;
                }
            }
#pragma unroll
            for (int i = 0; i < 4; i++)
#pragma unroll
                for (int j = 0; j < 8; j++)
                    mma_f16(acc[i][j], afr[i], bfr[j]);
        }
    }

    // ---- epilogue
    __half* Ch = (__half*)Cout + (OUT_HALF ? (long long)bz * sC : 0);
    float*  Cf = (float*)Cout + (OUT_HALF ? 0 : (long long)bz * sC);
#pragma unroll
    for (int i = 0; i < 4; i++) {
        int row0 = rowBase + warpM * 64 + i * 16 + lq;
#pragma unroll
        for (int j = 0; j < 8; j++) {
            int col = colBase + warpN * 64 + j * 8 + lr * 2;
            float b0 = 0.f, b1 = 0.f;
            if (BIAS) { b0 = bias[col]; b1 = bias[col + 1]; }
#pragma unroll
            for (int h = 0; h < 2; h++) {       // h=0: row0, h=1: row0+8
                float vx = acc[i][j][2 * h + 0] * alpha + b0;
                float vy = acc[i][j][2 * h + 1] * alpha + b1;
                if (RELU) { vx = fmaxf(vx, 0.f); vy = fmaxf(vy, 0.f); }
                long long r = (long long)(row0 + 8 * h) * N + col;
                if (OUT_HALF) *(__half2*)&Ch[r] = __floats2half2_rn(vx, vy);
                else          *(float2*)&Cf[r]  = make_float2(vx, vy);
            }
        }
    }
}

// ---------------------------------------------------------------------------
// f32 -> fp16 convert
// ---------------------------------------------------------------------------
__global__ void __launch_bounds__(256)
f2h_kernel(const float* __restrict__ in, __half* __restrict__ out, long long n)
{
    long long i = ((long long)blockIdx.x * blockDim.x + threadIdx.x) * 4;
    if (i >= n) return;
    float4 v = *(const float4*)&in[i];
    __half2 h0 = __floats2half2_rn(v.x, v.y);
    __half2 h1 = __floats2half2_rn(v.z, v.w);
    *(__half2*)&out[i]     = h0;
    *(__half2*)&out[i + 2] = h1;
}

// ---------------------------------------------------------------------------
// Transpose f32 [z][R][C] -> fp16 [z][C][R]  (weights only; tiny)
// ---------------------------------------------------------------------------
__global__ void __launch_bounds__(256)
transpose_f2h_kernel(const float* __restrict__ in, __half* __restrict__ out,
                     int R, int Cc)
{
    __shared__ float t[32][33];
    long long zi = (long long)blockIdx.z * R * Cc;
    int r0 = blockIdx.y * 32, c0 = blockIdx.x * 32;
    int tx = threadIdx.x & 31, ty = threadIdx.x >> 5;
#pragma unroll
    for (int i = 0; i < 4; i++)
        t[ty + i * 8][tx] = in[zi + (long long)(r0 + ty + i * 8) * Cc + c0 + tx];
    __syncthreads();
#pragma unroll
    for (int i = 0; i < 4; i++)
        out[zi + (long long)(c0 + ty + i * 8) * R + r0 + tx] =
            __float2half_rn(t[tx][ty + i * 8]);
}

// ---------------------------------------------------------------------------
// Block reductions (blockDim.x == 256)
// ---------------------------------------------------------------------------
__device__ __forceinline__ float block_reduce_max(float v, float* red) {
    int lane = threadIdx.x & 31, wid = threadIdx.x >> 5;
#pragma unroll
    for (int o = 16; o > 0; o >>= 1) v = fmaxf(v, __shfl_xor_sync(0xffffffffu, v, o));
    if (lane == 0) red[wid] = v;
    __syncthreads();
    if (wid == 0) {
        float x = (lane < 8) ? red[lane] : -INFINITY;
#pragma unroll
        for (int o = 4; o > 0; o >>= 1) x = fmaxf(x, __shfl_xor_sync(0xffffffffu, x, o));
        if (lane == 0) red[0] = x;
    }
    __syncthreads();
    float r = red[0];
    __syncthreads();
    return r;
}
__device__ __forceinline__ float block_reduce_sum(float v, float* red) {
    int lane = threadIdx.x & 31, wid = threadIdx.x >> 5;
#pragma unroll
    for (int o = 16; o > 0; o >>= 1) v += __shfl_xor_sync(0xffffffffu, v, o);
    if (lane == 0) red[wid] = v;
    __syncthreads();
    if (wid == 0) {
        float x = (lane < 8) ? red[lane] : 0.f;
#pragma unroll
        for (int o = 4; o > 0; o >>= 1) x += __shfl_xor_sync(0xffffffffu, x, o);
        if (lane == 0) red[0] = x;
    }
    __syncthreads();
    float r = red[0];
    __syncthreads();
    return r;
}

// ---------------------------------------------------------------------------
// Masked softmax: reads f32 scores + rel mask, writes fp16 attn.
// ---------------------------------------------------------------------------
__global__ void __launch_bounds__(256)
softmax_mask_kernel(const float* __restrict__ S, const float* __restrict__ rel,
                    __half* __restrict__ Sh)
{
    __shared__ float red[8];
    long long row = blockIdx.x;
    const float* s = S + row * 1024;
    const float* r = rel + row * 1024;
    int tid = threadIdx.x;

    float4 sv = *(const float4*)&s[tid * 4];
    float4 mv = *(const float4*)&r[tid * 4];
    float v0 = (mv.x != 0.f) ? sv.x : -INFINITY;
    float v1 = (mv.y != 0.f) ? sv.y : -INFINITY;
    float v2 = (mv.z != 0.f) ? sv.z : -INFINITY;
    float v3 = (mv.w != 0.f) ? sv.w : -INFINITY;

    float vmax = block_reduce_max(fmaxf(fmaxf(v0, v1), fmaxf(v2, v3)), red);

    float e0 = (mv.x != 0.f) ? expf(v0 - vmax) : 0.f;
    float e1 = (mv.y != 0.f) ? expf(v1 - vmax) : 0.f;
    float e2 = (mv.z != 0.f) ? expf(v2 - vmax) : 0.f;
    float e3 = (mv.w != 0.f) ? expf(v3 - vmax) : 0.f;

    float sum = block_reduce_sum(e0 + e1 + e2 + e3, red);
    float inv = (sum > 0.f) ? (1.f / sum) : 0.f;

    __half* o = Sh + row * 1024 + tid * 4;
    *(__half2*)&o[0] = __floats2half2_rn(e0 * inv, e1 * inv);
    *(__half2*)&o[2] = __floats2half2_rn(e2 * inv, e3 * inv);
}

// ---------------------------------------------------------------------------
// LN(X_h + C2_f32): OUT_HALF -> X_h (fp16), else -> float out.
// ---------------------------------------------------------------------------
template <bool OUT_HALF>
__global__ void __launch_bounds__(256)
add_ln_kernel(const __half* __restrict__ X, const float* __restrict__ Cx,
              const float* __restrict__ g, const float* __restrict__ b,
              void* __restrict__ outv)
{
    __shared__ float red[8];
    long long row = blockIdx.x;
    int tid = threadIdx.x;

    __half2 x0 = *(const __half2*)&X[row * 1024 + tid * 4];
    __half2 x1 = *(const __half2*)&X[row * 1024 + tid * 4 + 2];
    float4 cv = *(const float4*)&Cx[row * 1024 + tid * 4];
    float v0 = __low2float(x0)  + cv.x, v1 = __high2float(x0) + cv.y;
    float v2 = __low2float(x1)  + cv.z, v3 = __high2float(x1) + cv.w;

    float sum  = block_reduce_sum(v0 + v1 + v2 + v3, red);
    float ssq  = block_reduce_sum(v0 * v0 + v1 * v1 + v2 * v2 + v3 * v3, red);
    float mean = sum * (1.f / 1024.f);
    float var  = ssq * (1.f / 1024.f) - mean * mean;
    float rstd = rsqrtf(var + 1e-5f);

    float4 gv = *(const float4*)&g[tid * 4];
    float4 bv = *(const float4*)&b[tid * 4];
    float o0 = (v0 - mean) * rstd * gv.x + bv.x;
    float o1 = (v1 - mean) * rstd * gv.y + bv.y;
    float o2 = (v2 - mean) * rstd * gv.z + bv.z;
    float o3 = (v3 - mean) * rstd * gv.w + bv.w;

    if (OUT_HALF) {
        __half* o = (__half*)outv + row * 1024 + tid * 4;
        *(__half2*)&o[0] = __floats2half2_rn(o0, o1);
        *(__half2*)&o[2] = __floats2half2_rn(o2, o3);
    } else {
        float4 o; o.x = o0; o.y = o1; o.z = o2; o.w = o3;
        *(float4*)((float*)outv + row * 1024 + tid * 4) = o;
    }
}

// ---------------------------------------------------------------------------
extern "C" void kernel_launch(void* const* d_in, const int* in_sizes, int n_in,
                              void* d_out, int out_size)
{
    const float* node_fts = (const float*)d_in[0];
    const float* rel      = (const float*)d_in[1];
    const float* W_emb    = (const float*)d_in[2];
    const float* b_emb    = (const float*)d_in[3];
    const float* Wq       = (const float*)d_in[4];
    const float* bq       = (const float*)d_in[5];
    const float* Wk       = (const float*)d_in[6];
    const float* bk       = (const float*)d_in[7];
    const float* Wc       = (const float*)d_in[8];
    const float* ln_g     = (const float*)d_in[9];
    const float* ln_b     = (const float*)d_in[10];
    float* out = (float*)d_out;

    __half *Xh, *Qh, *Kh, *Sh, *Ch, *NFh, *Wh;
    float *S, *C2;
    cudaGetSymbolAddress((void**)&Xh,  g_Xh);
    cudaGetSymbolAddress((void**)&Qh,  g_Qh);
    cudaGetSymbolAddress((void**)&Kh,  g_Kh);
    cudaGetSymbolAddress((void**)&S,   g_S);
    cudaGetSymbolAddress((void**)&Sh,  g_Sh);
    cudaGetSymbolAddress((void**)&Ch,  g_Ch);
    cudaGetSymbolAddress((void**)&C2,  g_C2);
    cudaGetSymbolAddress((void**)&NFh, g_NFh);
    cudaGetSymbolAddress((void**)&Wh,  g_Wh);

    static bool attr_done = false;
    if (!attr_done) {
        cudaFuncSetAttribute(gemm_h<false, true,  true,  true >,
                             cudaFuncAttributeMaxDynamicSharedMemorySize, SMEM_BYTES);
        cudaFuncSetAttribute(gemm_h<false, false, true,  true >,
                             cudaFuncAttributeMaxDynamicSharedMemorySize, SMEM_BYTES);
        cudaFuncSetAttribute(gemm_h<false, false, false, false>,
                             cudaFuncAttributeMaxDynamicSharedMemorySize, SMEM_BYTES);
        cudaFuncSetAttribute(gemm_h<true,  false, false, true >,
                             cudaFuncAttributeMaxDynamicSharedMemorySize, SMEM_BYTES);
        cudaFuncSetAttribute(gemm_h<false, false, false, true >,
                             cudaFuncAttributeMaxDynamicSharedMemorySize, SMEM_BYTES);
        attr_done = true;
    }

    dim3 blk(256);
    const float inv_sqrt_dff = 1.0f / sqrtf((float)DFF);

    // fp16 transposed weights packed in g_Wh ([N][K] layouts)
    __half* WembT = Wh;                     // [1024,1024]
    __half* WqT   = Wh + 1024ll * 1024;     // [2][512,1024]
    __half* WkT   = Wh + 2048ll * 1024;     // [2][512,1024]
    __half* WcT   = Wh + 3072ll * 1024;     // [2][1024,1024]

    f2h_kernel<<<(int)(MTOT * DD / 1024), blk>>>(node_fts, NFh, MTOT * DD);
    transpose_f2h_kernel<<<dim3(32, 32, 1), blk>>>(W_emb, WembT, 1024, 1024);
    transpose_f2h_kernel<<<dim3(16, 32, 2), blk>>>(Wq, WqT, 1024, 512);
    transpose_f2h_kernel<<<dim3(16, 32, 2), blk>>>(Wk, WkT, 1024, 512);
    transpose_f2h_kernel<<<dim3(32, 32, 2), blk>>>(Wc, WcT, 1024, 1024);

    // Embedding: X = h(relu(NF @ W_emb + b_emb))
    gemm_h<false, true, true, true>
        <<<dim3(DD / BN, (int)(MTOT / BM), 1), blk, SMEM_BYTES>>>(
            NFh, WembT, b_emb, Xh, (int)MTOT, DD, DD, 0, 0, 0, 1.0f);

    for (int l = 0; l < 2; l++) {
        const __half* WqTl = WqT + (long long)l * DD * DFF;
        const float*  bql  = bq + (long long)l * DFF;
        const __half* WkTl = WkT + (long long)l * DD * DFF;
        const float*  bkl  = bk + (long long)l * DFF;
        const __half* WcTl = WcT + (long long)l * DD * DD;
        const float*  gl   = ln_g + (long long)l * DD;
        const float*  bl   = ln_b + (long long)l * DD;

        // Q = h(X @ Wq + bq); K likewise
        gemm_h<false, false, true, true>
            <<<dim3(DFF / BN, (int)(MTOT / BM), 1), blk, SMEM_BYTES>>>(
                Xh, WqTl, bql, Qh, (int)MTOT, DFF, DD, 0, 0, 0, 1.0f);
        gemm_h<false, false, true, true>
            <<<dim3(DFF / BN, (int)(MTOT / BM), 1), blk, SMEM_BYTES>>>(
                Xh, WkTl, bkl, Kh, (int)MTOT, DFF, DD, 0, 0, 0, 1.0f);

        // S(f32) = (Q @ K^T) / sqrt(DFF)
        gemm_h<false, false, false, false>
            <<<dim3(NN_ / BN, NN_ / BM, BB), blk, SMEM_BYTES>>>(
                Qh, Kh, nullptr, S, NN_, NN_, DFF,
                (long long)NN_ * DFF, (long long)NN_ * DFF,
                (long long)NN_ * NN_, inv_sqrt_dff);

        // masked softmax -> fp16
        softmax_mask_kernel<<<(int)MTOT, blk>>>(S, rel, Sh);

        // C = h(S @ X)  (B = X in [K][N] layout, ldmatrix.trans path)
        gemm_h<true, false, false, true>
            <<<dim3(DD / BN, NN_ / BM, BB), blk, SMEM_BYTES>>>(
                Sh, Xh, nullptr, Ch, NN_, DD, NN_,
                (long long)NN_ * NN_, (long long)NN_ * DD,
                (long long)NN_ * DD, 1.0f);

        // C2(f32) = C @ Wc
        gemm_h<false, false, false, false>
            <<<dim3(DD / BN, (int)(MTOT / BM), 1), blk, SMEM_BYTES>>>(
                Ch, WcTl, nullptr, C2, (int)MTOT, DD, DD, 0, 0, 0, 1.0f);

        // X = LN(X + C2): layer0 -> fp16 X, layer1 -> f32 d_out
        if (l == 0) add_ln_kernel<true ><<<(int)MTOT, blk>>>(Xh, C2, gl, bl, Xh);
        else        add_ln_kernel<false><<<(int)MTOT, blk>>>(Xh, C2, gl, bl, out);
    }
}

// round 9
// speedup vs baseline: 1.9211x; 1.0379x over previous
#include <cuda_runtime.h>
#include <cuda_fp16.h>
#include <math.h>
#include <stdint.h>

// ---------------------------------------------------------------------------
// GCNEncoder on fp16 tensor cores (mma.m16n8k16, fp32 accum), cp.async
// 3-stage pipeline, ldmatrix fragment loads. Fused QK projection, bit-packed
// softmax mask, fp16 intermediates everywhere except raw scores (f32).
// Block tile 128(M) x 256(N) x 64(K); 8 warps (2m x 4n); warp tile 64x64.
// Shapes: B=32, N=1024, D=1024, D_FF=512, L=2.
// ---------------------------------------------------------------------------

#define BM 128
#define BN 256
#define A_BYTES     (128 * 144)            // A tile: 128 rows x 64 halves pad 144B
#define BNK_BYTES   (256 * 144)            // B [N][K] tile
#define STAGE_BYTES (A_BYTES + BNK_BYTES)  // 55296 (also >= B_KN: 64*528=33792+A)
#define NSTAGE 3
#define SMEM_BYTES  (NSTAGE * STAGE_BYTES) // 165888

static const int BB   = 32;
static const int NN_  = 1024;
static const int DD   = 1024;
static const int DFF  = 512;
static const long long MTOT = 32768;

// Scratch (device globals; no allocations allowed)
__device__ __half   g_Xh [32768ll * 1024];
__device__ __half   g_QKh[32768ll * 1024];   // [ Q | K ] fused, 512+512 cols
__device__ float    g_S  [32ll * 1024 * 1024];
__device__ __half   g_Sh [32ll * 1024 * 1024];
__device__ __half   g_Ch [32768ll * 1024];
__device__ __half   g_C2h[32768ll * 1024];
__device__ __half   g_NFh[32768ll * 1024];
__device__ __half   g_Wh [5ll * 1024 * 1024]; // WembT 1M | WqkT 2M | WcT 2M
__device__ float    g_bqk[2 * 1024];
__device__ uint32_t g_mask[32768ll * 32];     // 1024 bits per row

// ---------------------------------------------------------------------------
__device__ __forceinline__ void cp_async16(uint32_t saddr, const void* g) {
    asm volatile("cp.async.cg.shared.global [%0], [%1], 16;\n" :: "r"(saddr), "l"(g));
}
__device__ __forceinline__ void cp_commit() {
    asm volatile("cp.async.commit_group;\n" ::: "memory");
}
template <int N>
__device__ __forceinline__ void cp_wait() {
    asm volatile("cp.async.wait_group %0;\n" :: "n"(N) : "memory");
}
__device__ __forceinline__ void ldsm_x4(uint32_t& r0, uint32_t& r1,
                                        uint32_t& r2, uint32_t& r3, uint32_t a) {
    asm volatile("ldmatrix.sync.aligned.m8n8.x4.shared.b16 {%0,%1,%2,%3}, [%4];"
                 : "=r"(r0), "=r"(r1), "=r"(r2), "=r"(r3) : "r"(a));
}
__device__ __forceinline__ void ldsm_x4_t(uint32_t& r0, uint32_t& r1,
                                          uint32_t& r2, uint32_t& r3, uint32_t a) {
    asm volatile("ldmatrix.sync.aligned.m8n8.x4.trans.shared.b16 {%0,%1,%2,%3}, [%4];"
                 : "=r"(r0), "=r"(r1), "=r"(r2), "=r"(r3) : "r"(a));
}
__device__ __forceinline__ void mma_f16(float c[4], const uint32_t a[4],
                                        const uint32_t b[2]) {
    asm volatile(
        "mma.sync.aligned.m16n8k16.row.col.f32.f16.f16.f32 "
        "{%0,%1,%2,%3}, {%4,%5,%6,%7}, {%8,%9}, {%0,%1,%2,%3};\n"
        : "+f"(c[0]), "+f"(c[1]), "+f"(c[2]), "+f"(c[3])
        : "r"(a[0]), "r"(a[1]), "r"(a[2]), "r"(a[3]),
          "r"(b[0]), "r"(b[1]));
}

// ---------------------------------------------------------------------------
// fp16 GEMM. C = alpha * A(MxK) @ B (+bias)(+relu); OUT_HALF picks C dtype.
// B_KN=false: B is [N][K]-ish with row stride ldb -> plain ldmatrix.
// B_KN=true : B is [K][N] with row stride ldb   -> ldmatrix.trans.
// A row stride lda. M%128==0, N%256==0, K%64==0. 256 threads.
// ---------------------------------------------------------------------------
template <bool B_KN, bool RELU, bool BIAS, bool OUT_HALF>
__global__ void __launch_bounds__(256, 1)
gemm_h(const __half* __restrict__ A, const __half* __restrict__ B,
       const float* __restrict__ bias, void* __restrict__ Cout,
       int M, int N, int K, int lda, int ldb,
       long long sA, long long sB, long long sC, float alpha)
{
    extern __shared__ char smem[];
    const uint32_t sbase = (uint32_t)__cvta_generic_to_shared(smem);

    const int bz = blockIdx.z;
    A += (long long)bz * sA;
    B += (long long)bz * sB;

    const int tid  = threadIdx.x;
    const int lane = tid & 31;
    const int wid  = tid >> 5;
    const int warpM = wid >> 2;
    const int warpN = wid & 3;
    const int rowBase = blockIdx.y * BM;
    const int colBase = blockIdx.x * BN;

    float acc[4][8][4];
#pragma unroll
    for (int i = 0; i < 4; i++)
#pragma unroll
        for (int j = 0; j < 8; j++)
#pragma unroll
            for (int r = 0; r < 4; r++) acc[i][j][r] = 0.f;

    const int lq = lane >> 2;
    const int lr = lane & 3;

    const int ofsA = ((lane & 7) + ((lane >> 3) & 1) * 8) * 144
                   + ((lane >> 4) & 1) * 16;
    const int ofsT = ((lane & 7) + ((lane >> 4) & 1) * 8) * 528
                   + ((lane >> 3) & 1) * 16;

    const int kTiles = K / 64;

    auto issue_stage = [&](int it) {
        const uint32_t sb = sbase + (it % NSTAGE) * STAGE_BYTES;
        const int k0 = it * 64;
#pragma unroll
        for (int i = 0; i < 4; i++) {
            int gid = tid + i * 256;
            int r = gid >> 3, c = gid & 7;
            cp_async16(sb + r * 144 + c * 16,
                       &A[(long long)(rowBase + r) * lda + k0 + c * 8]);
        }
        if (!B_KN) {
#pragma unroll
            for (int i = 0; i < 8; i++) {
                int gid = tid + i * 256;
                int r = gid >> 3, c = gid & 7;
                cp_async16(sb + A_BYTES + r * 144 + c * 16,
                           &B[(long long)(colBase + r) * ldb + k0 + c * 8]);
            }
        } else {
#pragma unroll
            for (int i = 0; i < 8; i++) {
                int gid = tid + i * 256;
                int r = gid >> 5, c = gid & 31;
                cp_async16(sb + A_BYTES + r * 528 + c * 16,
                           &B[(long long)(k0 + r) * ldb + colBase + c * 8]);
            }
        }
        cp_commit();
    };

    issue_stage(0);
    issue_stage(1);

    for (int it = 0; it < kTiles; it++) {
        if (it + 1 < kTiles) cp_wait<1>(); else cp_wait<0>();
        __syncthreads();
        if (it + 2 < kTiles) issue_stage(it + 2);

        const uint32_t sA_ = sbase + (it % NSTAGE) * STAGE_BYTES;
        const uint32_t sB_ = sA_ + A_BYTES;

#pragma unroll
        for (int ks = 0; ks < 4; ks++) {
            uint32_t afr[4][4];
#pragma unroll
            for (int i = 0; i < 4; i++) {
                uint32_t addr = sA_ + (uint32_t)((warpM * 64 + i * 16) * 144
                                                 + ks * 32 + ofsA);
                ldsm_x4(afr[i][0], afr[i][1], afr[i][2], afr[i][3], addr);
            }
            uint32_t bfr[8][2];
            if (!B_KN) {
#pragma unroll
                for (int p = 0; p < 4; p++) {
                    uint32_t addr = sB_ + (uint32_t)((warpN * 64 + p * 16) * 144
                                                     + ks * 32 + ofsA);
                    uint32_t r0, r1, r2, r3;
                    ldsm_x4(r0, r1, r2, r3, addr);
                    bfr[2 * p][0] = r0; bfr[2 * p + 1][0] = r1;
                    bfr[2 * p][1] = r2; bfr[2 * p + 1][1] = r3;
                }
            } else {
#pragma unroll
                for (int p = 0; p < 4; p++) {
                    uint32_t addr = sB_ + (uint32_t)(ks * 16 * 528
                                                     + (warpN * 64 + p * 16) * 2 + ofsT);
                    uint32_t r0, r1, r2, r3;
                    ldsm_x4_t(r0, r1, r2, r3, addr);
                    bfr[2 * p][0] = r0; bfr[2 * p + 1][0] = r1;
                    bfr[2 * p][1] = r2; bfr[2 * p + 1][1] = r3;
                }
            }
#pragma unroll
            for (int i = 0; i < 4; i++)
#pragma unroll
                for (int j = 0; j < 8; j++)
                    mma_f16(acc[i][j], afr[i], bfr[j]);
        }
    }

    // ---- epilogue
    __half* Ch = (__half*)Cout + (OUT_HALF ? (long long)bz * sC : 0);
    float*  Cf = (float*)Cout + (OUT_HALF ? 0 : (long long)bz * sC);
#pragma unroll
    for (int i = 0; i < 4; i++) {
        int row0 = rowBase + warpM * 64 + i * 16 + lq;
#pragma unroll
        for (int j = 0; j < 8; j++) {
            int col = colBase + warpN * 64 + j * 8 + lr * 2;
            float b0 = 0.f, b1 = 0.f;
            if (BIAS) { b0 = bias[col]; b1 = bias[col + 1]; }
#pragma unroll
            for (int h = 0; h < 2; h++) {
                float vx = acc[i][j][2 * h + 0] * alpha + b0;
                float vy = acc[i][j][2 * h + 1] * alpha + b1;
                if (RELU) { vx = fmaxf(vx, 0.f); vy = fmaxf(vy, 0.f); }
                long long r = (long long)(row0 + 8 * h) * N + col;
                if (OUT_HALF) *(__half2*)&Ch[r] = __floats2half2_rn(vx, vy);
                else          *(float2*)&Cf[r]  = make_float2(vx, vy);
            }
        }
    }
}

// ---------------------------------------------------------------------------
// f32 -> fp16 convert
// ---------------------------------------------------------------------------
__global__ void __launch_bounds__(256)
f2h_kernel(const float* __restrict__ in, __half* __restrict__ out, long long n)
{
    long long i = ((long long)blockIdx.x * blockDim.x + threadIdx.x) * 4;
    if (i >= n) return;
    float4 v = *(const float4*)&in[i];
    *(__half2*)&out[i]     = __floats2half2_rn(v.x, v.y);
    *(__half2*)&out[i + 2] = __floats2half2_rn(v.z, v.w);
}

// ---------------------------------------------------------------------------
// Transpose f32 [z][R][C] -> fp16 [z][C][R] (weights only)
// ---------------------------------------------------------------------------
__global__ void __launch_bounds__(256)
transpose_f2h_kernel(const float* __restrict__ in, __half* __restrict__ out,
                     int R, int Cc, long long ostride)
{
    __shared__ float t[32][33];
    long long zi = (long long)blockIdx.z * R * Cc;
    long long zo = (long long)blockIdx.z * ostride;
    int r0 = blockIdx.y * 32, c0 = blockIdx.x * 32;
    int tx = threadIdx.x & 31, ty = threadIdx.x >> 5;
#pragma unroll
    for (int i = 0; i < 4; i++)
        t[ty + i * 8][tx] = in[zi + (long long)(r0 + ty + i * 8) * Cc + c0 + tx];
    __syncthreads();
#pragma unroll
    for (int i = 0; i < 4; i++)
        out[zo + (long long)(c0 + ty + i * 8) * R + r0 + tx] =
            __float2half_rn(t[tx][ty + i * 8]);
}

// ---------------------------------------------------------------------------
// Bias concat: bqk[l][0:512)=bq[l], [512:1024)=bk[l]
// ---------------------------------------------------------------------------
__global__ void __launch_bounds__(256)
bias_concat_kernel(const float* __restrict__ bq, const float* __restrict__ bk,
                   float* __restrict__ bqk)
{
    int i = blockIdx.x * 256 + threadIdx.x;   // 0..2047
    if (i >= 2048) return;
    int l = i >> 10, j = i & 1023;
    bqk[i] = (j < 512) ? bq[l * 512 + j] : bk[l * 512 + j - 512];
}

// ---------------------------------------------------------------------------
// Pack rel != 0 into bit mask: 32 words per 1024-wide row.
// Block 256 = 8 warps, one row per warp; 32 ballot rounds per row.
// ---------------------------------------------------------------------------
__global__ void __launch_bounds__(256)
mask_pack_kernel(const float* __restrict__ rel, uint32_t* __restrict__ mask)
{
    int lane = threadIdx.x & 31;
    long long row = (long long)blockIdx.x * 8 + (threadIdx.x >> 5);
    const float* r = rel + row * 1024;
    uint32_t* m = mask + row * 32;
#pragma unroll
    for (int w = 0; w < 32; w++) {
        uint32_t bits = __ballot_sync(0xffffffffu, r[w * 32 + lane] != 0.f);
        if (lane == 0) m[w] = bits;
    }
}

// ---------------------------------------------------------------------------
// Block reductions (blockDim.x == 256)
// ---------------------------------------------------------------------------
__device__ __forceinline__ float block_reduce_max(float v, float* red) {
    int lane = threadIdx.x & 31, wid = threadIdx.x >> 5;
#pragma unroll
    for (int o = 16; o > 0; o >>= 1) v = fmaxf(v, __shfl_xor_sync(0xffffffffu, v, o));
    if (lane == 0) red[wid] = v;
    __syncthreads();
    if (wid == 0) {
        float x = (lane < 8) ? red[lane] : -INFINITY;
#pragma unroll
        for (int o = 4; o > 0; o >>= 1) x = fmaxf(x, __shfl_xor_sync(0xffffffffu, x, o));
        if (lane == 0) red[0] = x;
    }
    __syncthreads();
    float r = red[0];
    __syncthreads();
    return r;
}
__device__ __forceinline__ float block_reduce_sum(float v, float* red) {
    int lane = threadIdx.x & 31, wid = threadIdx.x >> 5;
#pragma unroll
    for (int o = 16; o > 0; o >>= 1) v += __shfl_xor_sync(0xffffffffu, v, o);
    if (lane == 0) red[wid] = v;
    __syncthreads();
    if (wid == 0) {
        float x = (lane < 8) ? red[lane] : 0.f;
#pragma unroll
        for (int o = 4; o > 0; o >>= 1) x += __shfl_xor_sync(0xffffffffu, x, o);
        if (lane == 0) red[0] = x;
    }
    __syncthreads();
    float r = red[0];
    __syncthreads();
    return r;
}

// ---------------------------------------------------------------------------
// Masked softmax: f32 scores + bit mask -> fp16 attn.
// ---------------------------------------------------------------------------
__global__ void __launch_bounds__(256)
softmax_mask_kernel(const float* __restrict__ S, const uint32_t* __restrict__ mask,
                    __half* __restrict__ Sh)
{
    __shared__ float red[8];
    long long row = blockIdx.x;
    const float* s = S + row * 1024;
    int tid = threadIdx.x;

    uint32_t mw = mask[row * 32 + (tid >> 3)];
    int bb = (tid & 7) * 4;
    bool m0 = (mw >> (bb + 0)) & 1, m1 = (mw >> (bb + 1)) & 1;
    bool m2 = (mw >> (bb + 2)) & 1, m3 = (mw >> (bb + 3)) & 1;

    float4 sv = *(const float4*)&s[tid * 4];
    float v0 = m0 ? sv.x : -INFINITY;
    float v1 = m1 ? sv.y : -INFINITY;
    float v2 = m2 ? sv.z : -INFINITY;
    float v3 = m3 ? sv.w : -INFINITY;

    float vmax = block_reduce_max(fmaxf(fmaxf(v0, v1), fmaxf(v2, v3)), red);

    float e0 = m0 ? expf(v0 - vmax) : 0.f;
    float e1 = m1 ? expf(v1 - vmax) : 0.f;
    float e2 = m2 ? expf(v2 - vmax) : 0.f;
    float e3 = m3 ? expf(v3 - vmax) : 0.f;

    float sum = block_reduce_sum(e0 + e1 + e2 + e3, red);
    float inv = (sum > 0.f) ? (1.f / sum) : 0.f;

    __half* o = Sh + row * 1024 + tid * 4;
    *(__half2*)&o[0] = __floats2half2_rn(e0 * inv, e1 * inv);
    *(__half2*)&o[2] = __floats2half2_rn(e2 * inv, e3 * inv);
}

// ---------------------------------------------------------------------------
// LN(X_h + C2_h): OUT_HALF -> fp16 out, else f32 out.
// ---------------------------------------------------------------------------
template <bool OUT_HALF>
__global__ void __launch_bounds__(256)
add_ln_kernel(const __half* __restrict__ X, const __half* __restrict__ Cx,
              const float* __restrict__ g, const float* __restrict__ b,
              void* __restrict__ outv)
{
    __shared__ float red[8];
    long long row = blockIdx.x;
    int tid = threadIdx.x;

    __half2 x0 = *(const __half2*)&X[row * 1024 + tid * 4];
    __half2 x1 = *(const __half2*)&X[row * 1024 + tid * 4 + 2];
    __half2 c0 = *(const __half2*)&Cx[row * 1024 + tid * 4];
    __half2 c1 = *(const __half2*)&Cx[row * 1024 + tid * 4 + 2];
    float v0 = __low2float(x0) + __low2float(c0);
    float v1 = __high2float(x0) + __high2float(c0);
    float v2 = __low2float(x1) + __low2float(c1);
    float v3 = __high2float(x1) + __high2float(c1);

    float sum  = block_reduce_sum(v0 + v1 + v2 + v3, red);
    float ssq  = block_reduce_sum(v0 * v0 + v1 * v1 + v2 * v2 + v3 * v3, red);
    float mean = sum * (1.f / 1024.f);
    float var  = ssq * (1.f / 1024.f) - mean * mean;
    float rstd = rsqrtf(var + 1e-5f);

    float4 gv = *(const float4*)&g[tid * 4];
    float4 bv = *(const float4*)&b[tid * 4];
    float o0 = (v0 - mean) * rstd * gv.x + bv.x;
    float o1 = (v1 - mean) * rstd * gv.y + bv.y;
    float o2 = (v2 - mean) * rstd * gv.z + bv.z;
    float o3 = (v3 - mean) * rstd * gv.w + bv.w;

    if (OUT_HALF) {
        __half* o = (__half*)outv + row * 1024 + tid * 4;
        *(__half2*)&o[0] = __floats2half2_rn(o0, o1);
        *(__half2*)&o[2] = __floats2half2_rn(o2, o3);
    } else {
        float4 o; o.x = o0; o.y = o1; o.z = o2; o.w = o3;
        *(float4*)((float*)outv + row * 1024 + tid * 4) = o;
    }
}

// ---------------------------------------------------------------------------
extern "C" void kernel_launch(void* const* d_in, const int* in_sizes, int n_in,
                              void* d_out, int out_size)
{
    const float* node_fts = (const float*)d_in[0];
    const float* rel      = (const float*)d_in[1];
    const float* W_emb    = (const float*)d_in[2];
    const float* b_emb    = (const float*)d_in[3];
    const float* Wq       = (const float*)d_in[4];
    const float* bq       = (const float*)d_in[5];
    const float* Wk       = (const float*)d_in[6];
    const float* bk       = (const float*)d_in[7];
    const float* Wc       = (const float*)d_in[8];
    const float* ln_g     = (const float*)d_in[9];
    const float* ln_b     = (const float*)d_in[10];
    float* out = (float*)d_out;

    __half *Xh, *QKh, *Sh, *Ch, *C2h, *NFh, *Wh;
    float *S, *bqk;
    uint32_t* Mk;
    cudaGetSymbolAddress((void**)&Xh,  g_Xh);
    cudaGetSymbolAddress((void**)&QKh, g_QKh);
    cudaGetSymbolAddress((void**)&S,   g_S);
    cudaGetSymbolAddress((void**)&Sh,  g_Sh);
    cudaGetSymbolAddress((void**)&Ch,  g_Ch);
    cudaGetSymbolAddress((void**)&C2h, g_C2h);
    cudaGetSymbolAddress((void**)&NFh, g_NFh);
    cudaGetSymbolAddress((void**)&Wh,  g_Wh);
    cudaGetSymbolAddress((void**)&bqk, g_bqk);
    cudaGetSymbolAddress((void**)&Mk,  g_mask);

    static bool attr_done = false;
    if (!attr_done) {
        cudaFuncSetAttribute(gemm_h<false, true,  true,  true >,
                             cudaFuncAttributeMaxDynamicSharedMemorySize, SMEM_BYTES);
        cudaFuncSetAttribute(gemm_h<false, false, true,  true >,
                             cudaFuncAttributeMaxDynamicSharedMemorySize, SMEM_BYTES);
        cudaFuncSetAttribute(gemm_h<false, false, false, false>,
                             cudaFuncAttributeMaxDynamicSharedMemorySize, SMEM_BYTES);
        cudaFuncSetAttribute(gemm_h<true,  false, false, true >,
                             cudaFuncAttributeMaxDynamicSharedMemorySize, SMEM_BYTES);
        cudaFuncSetAttribute(gemm_h<false, false, false, true >,
                             cudaFuncAttributeMaxDynamicSharedMemorySize, SMEM_BYTES);
        attr_done = true;
    }

    dim3 blk(256);
    const float inv_sqrt_dff = 1.0f / sqrtf((float)DFF);

    // fp16 transposed weights packed in g_Wh ([N][K] layouts)
    __half* WembT = Wh;                     // [1024][1024]
    __half* WqkT  = Wh + 1024ll * 1024;     // [2][1024][1024]: rows 0-511 Wq^T, 512-1023 Wk^T
    __half* WcT   = Wh + 3072ll * 1024;     // [2][1024][1024]

    // One-time prep
    f2h_kernel<<<(int)(MTOT * DD / 1024), blk>>>(node_fts, NFh, MTOT * DD);
    transpose_f2h_kernel<<<dim3(32, 32, 1), blk>>>(W_emb, WembT, 1024, 1024, 0);
    transpose_f2h_kernel<<<dim3(16, 32, 2), blk>>>(Wq, WqkT, 1024, 512,
                                                   1024ll * 1024);
    transpose_f2h_kernel<<<dim3(16, 32, 2), blk>>>(Wk, WqkT + 512ll * 1024,
                                                   1024, 512, 1024ll * 1024);
    transpose_f2h_kernel<<<dim3(32, 32, 2), blk>>>(Wc, WcT, 1024, 1024,
                                                   1024ll * 1024);
    bias_concat_kernel<<<8, blk>>>(bq, bk, bqk);
    mask_pack_kernel<<<(int)(MTOT / 8), blk>>>(rel, Mk);

    // Embedding: X = h(relu(NF @ W_emb + b_emb))
    gemm_h<false, true, true, true>
        <<<dim3(DD / BN, (int)(MTOT / BM), 1), blk, SMEM_BYTES>>>(
            NFh, WembT, b_emb, Xh, (int)MTOT, DD, DD, DD, DD, 0, 0, 0, 1.0f);

    for (int l = 0; l < 2; l++) {
        const __half* WqkTl = WqkT + (long long)l * 1024 * 1024;
        const __half* WcTl  = WcT + (long long)l * DD * DD;
        const float*  bqkl  = bqk + (long long)l * 1024;
        const float*  gl    = ln_g + (long long)l * DD;
        const float*  bl    = ln_b + (long long)l * DD;

        // [Q|K] = h(X @ [Wq|Wk] + [bq|bk])   one GEMM, N=1024
        gemm_h<false, false, true, true>
            <<<dim3(1024 / BN, (int)(MTOT / BM), 1), blk, SMEM_BYTES>>>(
                Xh, WqkTl, bqkl, QKh, (int)MTOT, 1024, DD, DD, DD, 0, 0, 0, 1.0f);

        // S(f32) = (Q @ K^T) / sqrt(DFF); Q,K = strided views of QKh
        gemm_h<false, false, false, false>
            <<<dim3(NN_ / BN, NN_ / BM, BB), blk, SMEM_BYTES>>>(
                QKh, QKh + 512, nullptr, S, NN_, NN_, DFF, 1024, 1024,
                (long long)NN_ * 1024, (long long)NN_ * 1024,
                (long long)NN_ * NN_, inv_sqrt_dff);

        // masked softmax -> fp16 (bit-packed mask)
        softmax_mask_kernel<<<(int)MTOT, blk>>>(S, Mk, Sh);

        // C = h(S @ X)  (B = X in [K][N] layout, ldmatrix.trans)
        gemm_h<true, false, false, true>
            <<<dim3(DD / BN, NN_ / BM, BB), blk, SMEM_BYTES>>>(
                Sh, Xh, nullptr, Ch, NN_, DD, NN_, 1024, 1024,
                (long long)NN_ * NN_, (long long)NN_ * DD,
                (long long)NN_ * DD, 1.0f);

        // C2(fp16) = C @ Wc
        gemm_h<false, false, false, true>
            <<<dim3(DD / BN, (int)(MTOT / BM), 1), blk, SMEM_BYTES>>>(
                Ch, WcTl, nullptr, C2h, (int)MTOT, DD, DD, DD, DD, 0, 0, 0, 1.0f);

        // X = LN(X + C2): layer0 -> fp16 X, layer1 -> f32 d_out
        if (l == 0) add_ln_kernel<true ><<<(int)MTOT, blk>>>(Xh, C2h, gl, bl, Xh);
        else        add_ln_kernel<false><<<(int)MTOT, blk>>>(Xh, C2h, gl, bl, out);
    }
}